// round 1
// baseline (speedup 1.0000x reference)
#include <cuda_runtime.h>
#include <cstdint>

#define N_NODES 8192
#define N_EDGES 24576
#define D_FEAT  64
#define N_QUBITS 16
#define PI_F 3.14159265358979f

// Scratch (no device mallocs allowed)
__device__ int      g_idx_o[N_EDGES];
__device__ int      g_idx_i[N_EDGES];
__device__ unsigned g_min_bits;
__device__ unsigned g_max_bits;

__global__ void init_kernel() {
    g_min_bits = 0x7F800000u;  // +inf
    g_max_bits = 0x00000000u;  // 0.0f (relu outputs are >= 0)
}

// Coalesced float4 streaming scan of a one-hot-per-column incidence matrix.
// M is [N_NODES, N_EDGES] row-major; whenever a nonzero is seen at linear
// position p, its row index is p / N_EDGES and column (edge) is p % N_EDGES.
__global__ void scan_kernel(const float4* __restrict__ M,
                            int* __restrict__ idx,
                            long total4) {
    long i = (long)blockIdx.x * blockDim.x + threadIdx.x;
    long stride = (long)gridDim.x * blockDim.x;
    for (; i < total4; i += stride) {
        float4 v = M[i];
        if (v.x != 0.f || v.y != 0.f || v.z != 0.f || v.w != 0.f) {
            long base = i * 4;
            int n = (int)(base / N_EDGES);
            int e = (int)(base % N_EDGES);
            if (v.x != 0.f) idx[e + 0] = n;
            if (v.y != 0.f) idx[e + 1] = n;
            if (v.z != 0.f) idx[e + 2] = n;
            if (v.w != 0.f) idx[e + 3] = n;
        }
    }
}

// One thread per edge: gather X[src], X[tgt] (64 floats each), compute
// relu(B @ W_in + b) into d_out, and block-reduce min/max into globals.
__global__ void __launch_bounds__(128)
edge_mlp_kernel(const float* __restrict__ X,
                const float* __restrict__ W,   // [128,16] row-major
                const float* __restrict__ b,   // [16]
                const int*   __restrict__ idx_o,
                const int*   __restrict__ idx_i,
                float* __restrict__ out) {
    __shared__ float sW[2 * D_FEAT * N_QUBITS];   // 8 KB
    __shared__ float sb[N_QUBITS];
    __shared__ float s_min[4], s_max[4];

    int tid = threadIdx.x;
    for (int i = tid; i < 2 * D_FEAT * N_QUBITS; i += 128) sW[i] = W[i];
    if (tid < N_QUBITS) sb[tid] = b[tid];
    __syncthreads();

    int e = blockIdx.x * 128 + tid;

    float acc[N_QUBITS];
#pragma unroll
    for (int q = 0; q < N_QUBITS; q++) acc[q] = sb[q];

    const float4* xo = (const float4*)(X + (long)idx_o[e] * D_FEAT);
    const float4* xi = (const float4*)(X + (long)idx_i[e] * D_FEAT);

#pragma unroll
    for (int d4 = 0; d4 < D_FEAT / 4; d4++) {
        float4 v = xo[d4];
        const float* w0 = &sW[(d4 * 4 + 0) * N_QUBITS];
#pragma unroll
        for (int q = 0; q < N_QUBITS; q++) {
            acc[q] = fmaf(v.x, w0[q + 0 * N_QUBITS], acc[q]);
            acc[q] = fmaf(v.y, w0[q + 1 * N_QUBITS], acc[q]);
            acc[q] = fmaf(v.z, w0[q + 2 * N_QUBITS], acc[q]);
            acc[q] = fmaf(v.w, w0[q + 3 * N_QUBITS], acc[q]);
        }
    }
#pragma unroll
    for (int d4 = 0; d4 < D_FEAT / 4; d4++) {
        float4 v = xi[d4];
        const float* w0 = &sW[(D_FEAT + d4 * 4) * N_QUBITS];
#pragma unroll
        for (int q = 0; q < N_QUBITS; q++) {
            acc[q] = fmaf(v.x, w0[q + 0 * N_QUBITS], acc[q]);
            acc[q] = fmaf(v.y, w0[q + 1 * N_QUBITS], acc[q]);
            acc[q] = fmaf(v.z, w0[q + 2 * N_QUBITS], acc[q]);
            acc[q] = fmaf(v.w, w0[q + 3 * N_QUBITS], acc[q]);
        }
    }

    float tmin = 3.4e38f, tmax = 0.0f;
#pragma unroll
    for (int q = 0; q < N_QUBITS; q++) {
        float h = fmaxf(acc[q], 0.0f);   // relu
        acc[q] = h;
        tmin = fminf(tmin, h);
        tmax = fmaxf(tmax, h);
    }

    // store raw h (normalized later)
    float4* o4 = (float4*)(out + (long)e * N_QUBITS);
    o4[0] = make_float4(acc[0], acc[1], acc[2], acc[3]);
    o4[1] = make_float4(acc[4], acc[5], acc[6], acc[7]);
    o4[2] = make_float4(acc[8], acc[9], acc[10], acc[11]);
    o4[3] = make_float4(acc[12], acc[13], acc[14], acc[15]);

    // warp reduce
#pragma unroll
    for (int off = 16; off > 0; off >>= 1) {
        tmin = fminf(tmin, __shfl_xor_sync(0xFFFFFFFF, tmin, off));
        tmax = fmaxf(tmax, __shfl_xor_sync(0xFFFFFFFF, tmax, off));
    }
    int wid = tid >> 5, lid = tid & 31;
    if (lid == 0) { s_min[wid] = tmin; s_max[wid] = tmax; }
    __syncthreads();
    if (tid == 0) {
        float bmin = fminf(fminf(s_min[0], s_min[1]), fminf(s_min[2], s_min[3]));
        float bmax = fmaxf(fmaxf(s_max[0], s_max[1]), fmaxf(s_max[2], s_max[3]));
        // nonneg floats: uint bit pattern preserves ordering
        atomicMin(&g_min_bits, __float_as_uint(bmin));
        atomicMax(&g_max_bits, __float_as_uint(bmax));
    }
}

__global__ void norm_kernel(float4* __restrict__ out, int n4) {
    float lo = __uint_as_float(g_min_bits);
    float hi = __uint_as_float(g_max_bits);
    float s = PI_F / (hi - lo);
    int i = blockIdx.x * blockDim.x + threadIdx.x;
    if (i < n4) {
        float4 v = out[i];
        v.x = (v.x - lo) * s;
        v.y = (v.y - lo) * s;
        v.z = (v.z - lo) * s;
        v.w = (v.w - lo) * s;
        out[i] = v;
    }
}

extern "C" void kernel_launch(void* const* d_in, const int* in_sizes, int n_in,
                              void* d_out, int out_size) {
    const float* X    = (const float*)d_in[0];   // [8192, 64]
    const float* Ri   = (const float*)d_in[1];   // [8192, 24576]
    const float* Ro   = (const float*)d_in[2];   // [8192, 24576]
    const float* W_in = (const float*)d_in[3];   // [128, 16]
    const float* b_in = (const float*)d_in[4];   // [16]
    float* out = (float*)d_out;                  // [24576, 16]

    int* idx_o_ptr; cudaGetSymbolAddress((void**)&idx_o_ptr, g_idx_o);
    int* idx_i_ptr; cudaGetSymbolAddress((void**)&idx_i_ptr, g_idx_i);

    init_kernel<<<1, 1>>>();

    const long total4 = (long)N_NODES * N_EDGES / 4;   // 50,331,648 float4s
    const int scan_blocks = 148 * 16;
    scan_kernel<<<scan_blocks, 256>>>((const float4*)Ro, idx_o_ptr, total4);
    scan_kernel<<<scan_blocks, 256>>>((const float4*)Ri, idx_i_ptr, total4);

    edge_mlp_kernel<<<N_EDGES / 128, 128>>>(X, W_in, b_in, idx_o_ptr, idx_i_ptr, out);

    const int n4 = N_EDGES * N_QUBITS / 4;   // 98,304
    norm_kernel<<<(n4 + 255) / 256, 256>>>((float4*)out, n4);
}